// round 10
// baseline (speedup 1.0000x reference)
#include <cuda_runtime.h>
#include <cstdint>
#include <math_constants.h>

// piecewise_maxpool: conv_output [B=4096, S=256, F=256] f32, e1/e2 [B] i32
// out [B, 3*F]: seg0 = [0, e1], seg1 = (e1, e2], seg2 = (e2, S). Non-empty.
//
// R10: 3 stages x 8KB (24KB ring) at occ 8 -> 192 KB in-flight TMA bytes/SM
// (the depth of R4, the best-DRAM% config) combined with 1184 concurrent
// streams (the occupancy of R9, the best-time config). Explicit (stage,
// phase) cursor since 3 is not a power of two.

static constexpr int BATCH = 4096;
static constexpr int SEQ   = 256;
static constexpr int FILT  = 256;
static constexpr int CHUNK_POS   = 8;                          // positions per chunk
static constexpr int CHUNK_BYTES = CHUNK_POS * FILT * 4;       // 8192
static constexpr int CHUNK_F4    = CHUNK_BYTES / 16;           // 512 float4
static constexpr int NCHUNK      = SEQ / CHUNK_POS;            // 32
static constexpr int STAGES      = 3;

__device__ __forceinline__ uint32_t smem_u32(const void* p) {
    return (uint32_t)__cvta_generic_to_shared(p);
}
__device__ __forceinline__ void mbar_init(uint32_t a, uint32_t n) {
    asm volatile("mbarrier.init.shared.b64 [%0], %1;" :: "r"(a), "r"(n) : "memory");
}
__device__ __forceinline__ void mbar_expect_tx(uint32_t a, uint32_t bytes) {
    asm volatile("mbarrier.arrive.expect_tx.shared.b64 _, [%0], %1;"
                 :: "r"(a), "r"(bytes) : "memory");
}
__device__ __forceinline__ void mbar_wait(uint32_t a, uint32_t parity) {
    uint32_t done;
    asm volatile(
        "{\n\t.reg .pred p;\n\t"
        "mbarrier.try_wait.parity.acquire.cta.shared::cta.b64 p, [%1], %2;\n\t"
        "selp.b32 %0, 1, 0, p;\n\t}"
        : "=r"(done) : "r"(a), "r"(parity) : "memory");
    if (!done) {
        asm volatile(
            "{\n\t.reg .pred P1;\n\t"
            "WL_%=:\n\t"
            "mbarrier.try_wait.parity.acquire.cta.shared::cta.b64 P1, [%0], %1, 0x989680;\n\t"
            "@P1 bra.uni WD_%=;\n\t"
            "bra.uni WL_%=;\n\t"
            "WD_%=:\n\t}"
            :: "r"(a), "r"(parity) : "memory");
    }
}
__device__ __forceinline__ uint64_t make_evict_first_policy() {
    uint64_t pol;
    asm volatile("createpolicy.fractional.L2::evict_first.b64 %0, 1.0;"
                 : "=l"(pol));
    return pol;
}
__device__ __forceinline__ void bulk_ld_ef(uint32_t dst, const void* src,
                                           uint32_t bytes, uint32_t mbar,
                                           uint64_t pol) {
    asm volatile(
        "cp.async.bulk.shared::cta.global.mbarrier::complete_tx::bytes"
        ".L2::cache_hint [%0], [%1], %2, [%3], %4;"
        :: "r"(dst), "l"(src), "r"(bytes), "r"(mbar), "l"(pol) : "memory");
}

__device__ __forceinline__ float4 fmax4(float4 a, float4 b) {
    return make_float4(fmaxf(a.x, b.x), fmaxf(a.y, b.y),
                       fmaxf(a.z, b.z), fmaxf(a.w, b.w));
}

__global__ __launch_bounds__(256, 8)
void piecewise_maxpool_tma_kernel(const float* __restrict__ x,
                                  const int*   __restrict__ e1,
                                  const int*   __restrict__ e2,
                                  float*       __restrict__ out)
{
    __shared__ __align__(1024) float4 buf[STAGES][CHUNK_F4];   // 24 KB ring
    __shared__ uint64_t mbar[STAGES];

    const int b = blockIdx.x;
    const int t = threadIdx.x;
    const int g = t & 63;    // float4 column (filters 4g..4g+3)
    const int p = t >> 6;    // position sub-offset 0..3

    const int c1 = __ldg(&e1[b]);
    const int c2 = __ldg(&e2[b]);
    const char* __restrict__ src =
        reinterpret_cast<const char*>(x + (size_t)b * SEQ * FILT);

    uint64_t pol = 0;
    if (t == 0) {
        pol = make_evict_first_policy();
        #pragma unroll
        for (int s = 0; s < STAGES; ++s) mbar_init(smem_u32(&mbar[s]), 1);
        asm volatile("fence.proxy.async.shared::cta;" ::: "memory");
        #pragma unroll
        for (int s = 0; s < STAGES; ++s) {
            mbar_expect_tx(smem_u32(&mbar[s]), CHUNK_BYTES);
            bulk_ld_ef(smem_u32(&buf[s][0]), src + (size_t)s * CHUNK_BYTES,
                       CHUNK_BYTES, smem_u32(&mbar[s]), pol);
        }
    }
    __syncthreads();   // mbar init visible to all waiters

    const float4 ninf = make_float4(-CUDART_INF_F, -CUDART_INF_F,
                                    -CUDART_INF_F, -CUDART_INF_F);
    float4 m0 = ninf, m1 = ninf, m2 = ninf;

    // explicit cursor: stage in [0,3), phase flips on wrap
    int stage = 0, phase = 0;

    for (int c = 0; c < NCHUNK; ++c) {
        mbar_wait(smem_u32(&mbar[stage]), phase);

        // consume: thread covers local positions p and p+4 of this 8-pos chunk
        #pragma unroll
        for (int j = 0; j < CHUNK_POS / 4; ++j) {
            const int lp = p + 4 * j;
            const int gs = c * CHUNK_POS + lp;
            const float4 v = buf[stage][lp * 64 + g];
            const int seg = (gs > c1) + (gs > c2);   // warp-uniform
            if (seg == 0)      m0 = fmax4(m0, v);
            else if (seg == 1) m1 = fmax4(m1, v);
            else               m2 = fmax4(m2, v);
        }
        __syncthreads();   // stage fully consumed by all threads

        const int nc = c + STAGES;
        if (t == 0 && nc < NCHUNK) {
            asm volatile("fence.proxy.async.shared::cta;" ::: "memory");
            mbar_expect_tx(smem_u32(&mbar[stage]), CHUNK_BYTES);
            bulk_ld_ef(smem_u32(&buf[stage][0]), src + (size_t)nc * CHUNK_BYTES,
                       CHUNK_BYTES, smem_u32(&mbar[stage]), pol);
        }

        if (++stage == STAGES) { stage = 0; phase ^= 1; }
    }

    // Final reduction: reuse the ring buffer as scratch (3*256 float4 = 12 KB).
    float4* red = &buf[0][0];
    red[t]       = m0;
    red[256 + t] = m1;
    red[512 + t] = m2;
    __syncthreads();

    if (t < 192) {
        const int seg = t >> 6;
        const int gg  = t & 63;
        const float4* rs = red + seg * 256;
        float4 r = fmax4(fmax4(rs[gg],       rs[64 + gg]),
                         fmax4(rs[128 + gg], rs[192 + gg]));
        float4* __restrict__ o =
            reinterpret_cast<float4*>(out + (size_t)b * 3 * FILT + seg * FILT);
        o[gg] = r;
    }
}

extern "C" void kernel_launch(void* const* d_in, const int* in_sizes, int n_in,
                              void* d_out, int out_size)
{
    const float* x  = (const float*)d_in[0];
    const int*   e1 = (const int*)d_in[1];
    const int*   e2 = (const int*)d_in[2];
    float*       o  = (float*)d_out;

    piecewise_maxpool_tma_kernel<<<BATCH, 256>>>(x, e1, e2, o);
}

// round 11
// speedup vs baseline: 1.0145x; 1.0145x over previous
#include <cuda_runtime.h>
#include <cstdint>
#include <math_constants.h>

// piecewise_maxpool: conv_output [B=4096, S=256, F=256] f32, e1/e2 [B] i32
// out [B, 3*F]: seg0 = [0, e1], seg1 = (e1, e2], seg2 = (e2, S). Non-empty.
//
// FINAL (== R9, best measured 154.8 us): TMA bulk-copy ping-pong, 8KB x 2
// stages, occ 8, grid=4096, evict_first L2 hint. Converged at the LTS chip
// cap (~6300 B/cyc, path-independent): seven structural variants (chunk size
// 4/8/16KB, stages 2/3/4, occ 6/8, persistent vs one-shot, eviction policy)
// all measured 6.97-7.11 TB/s. Time floor at this cap ~151 us; this kernel
// is within 2.5% of it. TMA (vs LDG) was the one decisive win: it bypasses
// the L1tex/MSHR request path that capped the LDG version at 6.05 TB/s.

static constexpr int BATCH = 4096;
static constexpr int SEQ   = 256;
static constexpr int FILT  = 256;
static constexpr int CHUNK_POS   = 8;                          // positions per chunk
static constexpr int CHUNK_BYTES = CHUNK_POS * FILT * 4;       // 8192
static constexpr int CHUNK_F4    = CHUNK_BYTES / 16;           // 512 float4
static constexpr int NCHUNK      = SEQ / CHUNK_POS;            // 32
static constexpr int STAGES      = 2;

__device__ __forceinline__ uint32_t smem_u32(const void* p) {
    return (uint32_t)__cvta_generic_to_shared(p);
}
__device__ __forceinline__ void mbar_init(uint32_t a, uint32_t n) {
    asm volatile("mbarrier.init.shared.b64 [%0], %1;" :: "r"(a), "r"(n) : "memory");
}
__device__ __forceinline__ void mbar_expect_tx(uint32_t a, uint32_t bytes) {
    asm volatile("mbarrier.arrive.expect_tx.shared.b64 _, [%0], %1;"
                 :: "r"(a), "r"(bytes) : "memory");
}
__device__ __forceinline__ void mbar_wait(uint32_t a, uint32_t parity) {
    uint32_t done;
    asm volatile(
        "{\n\t.reg .pred p;\n\t"
        "mbarrier.try_wait.parity.acquire.cta.shared::cta.b64 p, [%1], %2;\n\t"
        "selp.b32 %0, 1, 0, p;\n\t}"
        : "=r"(done) : "r"(a), "r"(parity) : "memory");
    if (!done) {
        asm volatile(
            "{\n\t.reg .pred P1;\n\t"
            "WL_%=:\n\t"
            "mbarrier.try_wait.parity.acquire.cta.shared::cta.b64 P1, [%0], %1, 0x989680;\n\t"
            "@P1 bra.uni WD_%=;\n\t"
            "bra.uni WL_%=;\n\t"
            "WD_%=:\n\t}"
            :: "r"(a), "r"(parity) : "memory");
    }
}
__device__ __forceinline__ uint64_t make_evict_first_policy() {
    uint64_t pol;
    asm volatile("createpolicy.fractional.L2::evict_first.b64 %0, 1.0;"
                 : "=l"(pol));
    return pol;
}
__device__ __forceinline__ void bulk_ld_ef(uint32_t dst, const void* src,
                                           uint32_t bytes, uint32_t mbar,
                                           uint64_t pol) {
    asm volatile(
        "cp.async.bulk.shared::cta.global.mbarrier::complete_tx::bytes"
        ".L2::cache_hint [%0], [%1], %2, [%3], %4;"
        :: "r"(dst), "l"(src), "r"(bytes), "r"(mbar), "l"(pol) : "memory");
}

__device__ __forceinline__ float4 fmax4(float4 a, float4 b) {
    return make_float4(fmaxf(a.x, b.x), fmaxf(a.y, b.y),
                       fmaxf(a.z, b.z), fmaxf(a.w, b.w));
}

__global__ __launch_bounds__(256, 8)
void piecewise_maxpool_tma_kernel(const float* __restrict__ x,
                                  const int*   __restrict__ e1,
                                  const int*   __restrict__ e2,
                                  float*       __restrict__ out)
{
    __shared__ __align__(1024) float4 buf[STAGES][CHUNK_F4];   // 16 KB ring
    __shared__ uint64_t mbar[STAGES];

    const int b = blockIdx.x;
    const int t = threadIdx.x;
    const int g = t & 63;    // float4 column (filters 4g..4g+3)
    const int p = t >> 6;    // position sub-offset 0..3

    const int c1 = __ldg(&e1[b]);
    const int c2 = __ldg(&e2[b]);
    const char* __restrict__ src =
        reinterpret_cast<const char*>(x + (size_t)b * SEQ * FILT);

    uint64_t pol = 0;
    if (t == 0) {
        pol = make_evict_first_policy();
        #pragma unroll
        for (int s = 0; s < STAGES; ++s) mbar_init(smem_u32(&mbar[s]), 1);
        asm volatile("fence.proxy.async.shared::cta;" ::: "memory");
        #pragma unroll
        for (int s = 0; s < STAGES; ++s) {
            mbar_expect_tx(smem_u32(&mbar[s]), CHUNK_BYTES);
            bulk_ld_ef(smem_u32(&buf[s][0]), src + (size_t)s * CHUNK_BYTES,
                       CHUNK_BYTES, smem_u32(&mbar[s]), pol);
        }
    }
    __syncthreads();   // mbar init visible to all waiters

    const float4 ninf = make_float4(-CUDART_INF_F, -CUDART_INF_F,
                                    -CUDART_INF_F, -CUDART_INF_F);
    float4 m0 = ninf, m1 = ninf, m2 = ninf;

    for (int c = 0; c < NCHUNK; ++c) {
        const int s = c & (STAGES - 1);
        mbar_wait(smem_u32(&mbar[s]), (c >> 1) & 1);

        // consume: thread covers local positions p and p+4 of this 8-pos chunk
        #pragma unroll
        for (int j = 0; j < CHUNK_POS / 4; ++j) {
            const int lp = p + 4 * j;
            const int gs = c * CHUNK_POS + lp;
            const float4 v = buf[s][lp * 64 + g];
            const int seg = (gs > c1) + (gs > c2);   // warp-uniform
            if (seg == 0)      m0 = fmax4(m0, v);
            else if (seg == 1) m1 = fmax4(m1, v);
            else               m2 = fmax4(m2, v);
        }
        __syncthreads();   // stage s fully consumed by all threads

        const int nc = c + STAGES;
        if (t == 0 && nc < NCHUNK) {
            // generic reads of buf[s] by all threads are ordered before this
            // point by the BAR above; one proxy fence per refill orders them
            // against the async-proxy TMA overwrite.
            asm volatile("fence.proxy.async.shared::cta;" ::: "memory");
            mbar_expect_tx(smem_u32(&mbar[s]), CHUNK_BYTES);
            bulk_ld_ef(smem_u32(&buf[s][0]), src + (size_t)nc * CHUNK_BYTES,
                       CHUNK_BYTES, smem_u32(&mbar[s]), pol);
        }
    }

    // Final reduction: reuse the ring buffer as scratch (3*256 float4 = 12 KB).
    float4* red = &buf[0][0];
    red[t]       = m0;
    red[256 + t] = m1;
    red[512 + t] = m2;
    __syncthreads();

    if (t < 192) {
        const int seg = t >> 6;
        const int gg  = t & 63;
        const float4* rs = red + seg * 256;
        float4 r = fmax4(fmax4(rs[gg],       rs[64 + gg]),
                         fmax4(rs[128 + gg], rs[192 + gg]));
        float4* __restrict__ o =
            reinterpret_cast<float4*>(out + (size_t)b * 3 * FILT + seg * FILT);
        o[gg] = r;
    }
}

extern "C" void kernel_launch(void* const* d_in, const int* in_sizes, int n_in,
                              void* d_out, int out_size)
{
    const float* x  = (const float*)d_in[0];
    const int*   e1 = (const int*)d_in[1];
    const int*   e2 = (const int*)d_in[2];
    float*       o  = (float*)d_out;

    piecewise_maxpool_tma_kernel<<<BATCH, 256>>>(x, e1, e2, o);
}